// round 2
// baseline (speedup 1.0000x reference)
#include <cuda_runtime.h>
#include <cuda_fp16.h>
#include <cstdint>

#define NMAX 100000
#define EMAX 1000000
#define SA 132   // smem A row stride (floats): keeps LDS.128 16B-aligned, breaks STS conflicts

// -------- persistent device scratch (no allocations allowed) --------
__device__ __half  g_hs [NMAX * 64];  // scaled messages h*out_norm, fp16, 12.8 MB
__device__ float4  g_agg[NMAX * 16];  // edge aggregation buffer (fp32)
__device__ float4  g_h  [NMAX * 16];  // current layer activations
__device__ float4  g_hf [NMAX * 16];  // jumping-knowledge accumulator
__device__ float   g_onorm[NMAX];     // out-degree -> rsqrt norm (in place)
__device__ float   g_inorm[NMAX];     // in-degree  -> rsqrt norm (in place)

// -------- degree / norm kernels --------
__global__ void zero_deg_kernel(int n) {
    int i = blockIdx.x * blockDim.x + threadIdx.x;
    if (i < n) { g_onorm[i] = 0.f; g_inorm[i] = 0.f; }
}

__global__ void deg_kernel(const int* __restrict__ src, const int* __restrict__ dst, int e) {
    int i = blockIdx.x * blockDim.x + threadIdx.x;
    if (i < e) {
        atomicAdd(&g_onorm[src[i]], 1.0f);
        atomicAdd(&g_inorm[dst[i]], 1.0f);
    }
}

__global__ void norm_kernel(int n) {
    int i = blockIdx.x * blockDim.x + threadIdx.x;
    if (i < n) {
        g_onorm[i] = rsqrtf(fmaxf(g_onorm[i], 1.0f));
        g_inorm[i] = rsqrtf(fmaxf(g_inorm[i], 1.0f));
    }
}

// -------- layer-0 message prep: hs = fp16(feats * out_norm); agg = 0 --------
__global__ void conv0_kernel(const float4* __restrict__ feats4, int n8) {
    int i = blockIdx.x * blockDim.x + threadIdx.x;
    if (i >= n8) return;
    int node = i >> 3, q = i & 7;
    float s = g_onorm[node];
    float4 v0 = feats4[node * 16 + q * 2];
    float4 v1 = feats4[node * 16 + q * 2 + 1];
    __half2 a0 = __floats2half2_rn(v0.x * s, v0.y * s);
    __half2 a1 = __floats2half2_rn(v0.z * s, v0.w * s);
    __half2 a2 = __floats2half2_rn(v1.x * s, v1.y * s);
    __half2 a3 = __floats2half2_rn(v1.z * s, v1.w * s);
    uint4 u = make_uint4(*(uint32_t*)&a0, *(uint32_t*)&a1, *(uint32_t*)&a2, *(uint32_t*)&a3);
    *(uint4*)(g_hs + (size_t)node * 64 + q * 8) = u;
    float4 z = make_float4(0.f, 0.f, 0.f, 0.f);
    g_agg[node * 16 + q * 2]     = z;
    g_agg[node * 16 + q * 2 + 1] = z;
}

// -------- edge scatter: agg[dst] += hs[src]; 8 lanes per edge (16B fp16 load),
//          fp32 vector red for the accumulation --------
__global__ void edge_kernel(const int* __restrict__ src, const int* __restrict__ dst, int e8) {
    int i = blockIdx.x * blockDim.x + threadIdx.x;
    if (i >= e8) return;
    int e = i >> 3;
    int q = i & 7;
    int s = __ldg(src + e);
    int d = __ldg(dst + e);
    uint4 u = *(const uint4*)(g_hs + (size_t)s * 64 + q * 8);
    __half2 h0 = *(__half2*)&u.x, h1 = *(__half2*)&u.y;
    __half2 h2 = *(__half2*)&u.z, h3 = *(__half2*)&u.w;
    float2 f0 = __half22float2(h0), f1 = __half22float2(h1);
    float2 f2 = __half22float2(h2), f3 = __half22float2(h3);
    float* aggf = (float*)g_agg;
    float4* p = (float4*)(aggf + (size_t)d * 64 + q * 8);
    asm volatile("red.global.add.v4.f32 [%0], {%1, %2, %3, %4};"
                 :: "l"(p), "f"(f0.x), "f"(f0.y), "f"(f1.x), "f"(f1.y) : "memory");
    asm volatile("red.global.add.v4.f32 [%0], {%1, %2, %3, %4};"
                 :: "l"(p + 1), "f"(f2.x), "f"(f2.y), "f"(f3.x), "f"(f3.y) : "memory");
}

// -------- fused layer GEMM: t = [agg*in_norm | h] @ [convW; resW] + b ; LN ; relu ;
//          h <- t ; h_final (+)= t ; hs <- fp16(t*out_norm) ; agg <- 0 --------
__global__ __launch_bounds__(256, 2)
void fused_kernel(const float* __restrict__ h_ext, int use_ext,
                  const float* __restrict__ convW, const float* __restrict__ resW,
                  const float* __restrict__ conv_b, const float* __restrict__ res_b,
                  const float* __restrict__ ln_g,  const float* __restrict__ ln_b,
                  int n, int first, int write_hs)
{
    extern __shared__ float sm[];
    float* As = sm;               // [128][SA], k-major (transposed)
    float* Ws = sm + 128 * SA;    // [128][64]
    float* aggrw = (float*)g_agg;
    const float* h_in = use_ext ? h_ext : (const float*)g_h;

    int t = threadIdx.x;
    int base = blockIdx.x * 128;

    // load combined weight [convW ; resW] -> Ws[k][d]
    for (int i = t; i < 2048; i += 256) {
        int k = i >> 4, c4 = i & 15;
        const float* wsrc = (k < 64) ? (convW + k * 64) : (resW + (k - 64) * 64);
        *(float4*)(Ws + k * 64 + c4 * 4) = *(const float4*)(wsrc + c4 * 4);
    }
    // A first half: agg * in_norm, transposed into As[k][r]; zero agg behind us
    for (int i = t; i < 2048; i += 256) {
        int r = i >> 4, k4 = i & 15;
        int node = base + r;
        float4 v = make_float4(0.f, 0.f, 0.f, 0.f);
        float nn = 0.f;
        if (node < n) {
            v = *(const float4*)(aggrw + node * 64 + k4 * 4);
            nn = g_inorm[node];
            if (write_hs)   // zero for next layer's edge scatter
                *(float4*)(aggrw + node * 64 + k4 * 4) = make_float4(0.f, 0.f, 0.f, 0.f);
        }
        int k = k4 * 4;
        As[(k + 0) * SA + r] = v.x * nn;
        As[(k + 1) * SA + r] = v.y * nn;
        As[(k + 2) * SA + r] = v.z * nn;
        As[(k + 3) * SA + r] = v.w * nn;
    }
    // A second half: h
    for (int i = t; i < 2048; i += 256) {
        int r = i >> 4, k4 = i & 15;
        int node = base + r;
        float4 v = make_float4(0.f, 0.f, 0.f, 0.f);
        if (node < n) v = *(const float4*)(h_in + node * 64 + k4 * 4);
        int k = 64 + k4 * 4;
        As[(k + 0) * SA + r] = v.x;
        As[(k + 1) * SA + r] = v.y;
        As[(k + 2) * SA + r] = v.z;
        As[(k + 3) * SA + r] = v.w;
    }
    __syncthreads();

    int rg = t >> 3;      // 0..31 : rows rg*4 .. rg*4+3
    int cg = t & 7;       // 0..7  : cols cg*8 .. cg*8+7
    float acc[4][8];
#pragma unroll
    for (int r = 0; r < 4; r++)
#pragma unroll
        for (int c = 0; c < 8; c++) acc[r][c] = 0.f;

#pragma unroll 8
    for (int k = 0; k < 128; k++) {
        float4 a  = *(const float4*)(As + k * SA + rg * 4);
        float4 w0 = *(const float4*)(Ws + k * 64 + cg * 8);
        float4 w1 = *(const float4*)(Ws + k * 64 + cg * 8 + 4);
        float av[4] = {a.x, a.y, a.z, a.w};
        float wv[8] = {w0.x, w0.y, w0.z, w0.w, w1.x, w1.y, w1.z, w1.w};
#pragma unroll
        for (int r = 0; r < 4; r++)
#pragma unroll
            for (int c = 0; c < 8; c++)
                acc[r][c] += av[r] * wv[c];
    }

    // epilogue: bias, LayerNorm across 8 lanes (cg dim), relu, write h / h_final / hs
    int col0 = cg * 8;
    float bb[8], gg[8], lb[8];
#pragma unroll
    for (int c = 0; c < 8; c++) {
        bb[c] = conv_b[col0 + c] + res_b[col0 + c];
        gg[c] = ln_g[col0 + c];
        lb[c] = ln_b[col0 + c];
    }
    float* hout = (float*)g_h;
    float* hf   = (float*)g_hf;

#pragma unroll
    for (int r = 0; r < 4; r++) {
        float v[8]; float s = 0.f, sq = 0.f;
#pragma unroll
        for (int c = 0; c < 8; c++) {
            v[c] = acc[r][c] + bb[c];
            s += v[c]; sq += v[c] * v[c];
        }
#pragma unroll
        for (int m = 1; m < 8; m <<= 1) {
            s  += __shfl_xor_sync(0xffffffffu, s,  m);
            sq += __shfl_xor_sync(0xffffffffu, sq, m);
        }
        float mu  = s * (1.f / 64.f);
        float var = sq * (1.f / 64.f) - mu * mu;
        float inv = rsqrtf(var + 1e-5f);
        int node = base + rg * 4 + r;
        if (node < n) {
            float o[8];
#pragma unroll
            for (int c = 0; c < 8; c++) {
                float x = (v[c] - mu) * inv * gg[c] + lb[c];
                o[c] = fmaxf(x, 0.f);
            }
            float4 o0 = make_float4(o[0], o[1], o[2], o[3]);
            float4 o1 = make_float4(o[4], o[5], o[6], o[7]);
            *(float4*)(hout + node * 64 + col0)     = o0;
            *(float4*)(hout + node * 64 + col0 + 4) = o1;
            float4* fp = (float4*)(hf + node * 64 + col0);
            if (first) {
                fp[0] = o0; fp[1] = o1;
            } else {
                float4 a0 = fp[0], a1 = fp[1];
                a0.x += o0.x; a0.y += o0.y; a0.z += o0.z; a0.w += o0.w;
                a1.x += o1.x; a1.y += o1.y; a1.z += o1.z; a1.w += o1.w;
                fp[0] = a0; fp[1] = a1;
            }
            if (write_hs) {  // next layer's fp16 scaled messages
                float on = g_onorm[node];
                __half2 a0h = __floats2half2_rn(o[0] * on, o[1] * on);
                __half2 a1h = __floats2half2_rn(o[2] * on, o[3] * on);
                __half2 a2h = __floats2half2_rn(o[4] * on, o[5] * on);
                __half2 a3h = __floats2half2_rn(o[6] * on, o[7] * on);
                uint4 u = make_uint4(*(uint32_t*)&a0h, *(uint32_t*)&a1h,
                                     *(uint32_t*)&a2h, *(uint32_t*)&a3h);
                *(uint4*)(g_hs + (size_t)node * 64 + col0) = u;
            }
        }
    }
}

// -------- final prediction GEMM: out = h_final @ predW + pred_b (K = 64) --------
__global__ __launch_bounds__(256, 2)
void pred_kernel(const float* __restrict__ predW, const float* __restrict__ pred_b,
                 float* __restrict__ out, int n)
{
    extern __shared__ float sm[];
    float* As = sm;              // [64][SA]
    float* Ws = sm + 64 * SA;    // [64][64]
    const float* hfin = (const float*)g_hf;

    int t = threadIdx.x;
    int base = blockIdx.x * 128;

    for (int i = t; i < 1024; i += 256) {
        int k = i >> 4, c4 = i & 15;
        *(float4*)(Ws + k * 64 + c4 * 4) = *(const float4*)(predW + k * 64 + c4 * 4);
    }
    for (int i = t; i < 2048; i += 256) {
        int r = i >> 4, k4 = i & 15;
        int node = base + r;
        float4 v = make_float4(0.f, 0.f, 0.f, 0.f);
        if (node < n) v = *(const float4*)(hfin + node * 64 + k4 * 4);
        int k = k4 * 4;
        As[(k + 0) * SA + r] = v.x;
        As[(k + 1) * SA + r] = v.y;
        As[(k + 2) * SA + r] = v.z;
        As[(k + 3) * SA + r] = v.w;
    }
    __syncthreads();

    int rg = t >> 3, cg = t & 7;
    float acc[4][8];
#pragma unroll
    for (int r = 0; r < 4; r++)
#pragma unroll
        for (int c = 0; c < 8; c++) acc[r][c] = 0.f;

#pragma unroll 8
    for (int k = 0; k < 64; k++) {
        float4 a  = *(const float4*)(As + k * SA + rg * 4);
        float4 w0 = *(const float4*)(Ws + k * 64 + cg * 8);
        float4 w1 = *(const float4*)(Ws + k * 64 + cg * 8 + 4);
        float av[4] = {a.x, a.y, a.z, a.w};
        float wv[8] = {w0.x, w0.y, w0.z, w0.w, w1.x, w1.y, w1.z, w1.w};
#pragma unroll
        for (int r = 0; r < 4; r++)
#pragma unroll
            for (int c = 0; c < 8; c++)
                acc[r][c] += av[r] * wv[c];
    }

    int col0 = cg * 8;
    float bb[8];
#pragma unroll
    for (int c = 0; c < 8; c++) bb[c] = pred_b[col0 + c];

#pragma unroll
    for (int r = 0; r < 4; r++) {
        int node = base + rg * 4 + r;
        if (node < n) {
            float4 o0 = make_float4(acc[r][0] + bb[0], acc[r][1] + bb[1],
                                    acc[r][2] + bb[2], acc[r][3] + bb[3]);
            float4 o1 = make_float4(acc[r][4] + bb[4], acc[r][5] + bb[5],
                                    acc[r][6] + bb[6], acc[r][7] + bb[7]);
            *(float4*)(out + node * 64 + col0)     = o0;
            *(float4*)(out + node * 64 + col0 + 4) = o1;
        }
    }
}

// -------- host entry --------
extern "C" void kernel_launch(void* const* d_in, const int* in_sizes, int n_in,
                              void* d_out, int out_size)
{
    const float* feats  = (const float*)d_in[0];
    const int*   src    = (const int*)  d_in[1];
    const int*   dst    = (const int*)  d_in[2];
    const float* convW  = (const float*)d_in[3];   // [3][64][64]
    const float* conv_b = (const float*)d_in[4];   // [3][64]
    const float* resW   = (const float*)d_in[5];
    const float* res_b  = (const float*)d_in[6];
    const float* ln_g   = (const float*)d_in[7];
    const float* ln_b   = (const float*)d_in[8];
    const float* predW  = (const float*)d_in[9];
    const float* pred_b = (const float*)d_in[10];

    int n = in_sizes[0] / 64;
    int e = in_sizes[1];

    const int smem_fused = (128 * SA + 128 * 64) * 4;  // 100352 B
    const int smem_pred  = (64 * SA + 64 * 64) * 4;    //  50176 B
    cudaFuncSetAttribute(fused_kernel, cudaFuncAttributeMaxDynamicSharedMemorySize, smem_fused);
    cudaFuncSetAttribute(pred_kernel,  cudaFuncAttributeMaxDynamicSharedMemorySize, smem_pred);

    zero_deg_kernel<<<(n + 255) / 256, 256>>>(n);
    deg_kernel<<<(e + 255) / 256, 256>>>(src, dst, e);
    norm_kernel<<<(n + 255) / 256, 256>>>(n);

    int n8 = n * 8;
    int e8 = e * 8;
    int gb = (n + 127) / 128;

    conv0_kernel<<<(n8 + 255) / 256, 256>>>((const float4*)feats, n8);

    for (int l = 0; l < 3; l++) {
        int use_ext = (l == 0) ? 1 : 0;
        edge_kernel<<<(e8 + 255) / 256, 256>>>(src, dst, e8);
        fused_kernel<<<gb, 256, smem_fused>>>(feats, use_ext,
                                              convW + l * 4096, resW + l * 4096,
                                              conv_b + l * 64, res_b + l * 64,
                                              ln_g + l * 64, ln_b + l * 64,
                                              n, (l == 0) ? 1 : 0, (l < 2) ? 1 : 0);
    }
    pred_kernel<<<gb, 256, smem_pred>>>(predW, pred_b, (float*)d_out, n);
}

// round 3
// speedup vs baseline: 1.5276x; 1.5276x over previous
#include <cuda_runtime.h>
#include <cuda_fp16.h>
#include <cstdint>

#define NMAX 100000
#define EMAX 1000000
#define SA 132        // smem A row stride (floats)
#define NB_SCAN 128   // >= ceil(NMAX/1024)

// -------- persistent device scratch --------
__device__ __half  g_hs [NMAX * 64];   // scaled messages h*out_norm, fp16
__device__ float4  g_agg[NMAX * 16];   // aggregation result (fp32)
__device__ float4  g_h  [NMAX * 16];   // current layer activations
__device__ float4  g_hf [NMAX * 16];   // jumping-knowledge accumulator
__device__ float   g_onorm[NMAX];      // out-degree -> rsqrt norm
__device__ float   g_inorm[NMAX];      // in-degree  -> rsqrt norm
__device__ int     g_rowptr[NMAX + 1]; // dst-CSR row pointers
__device__ int     g_bsum[NB_SCAN];    // scan block sums
__device__ int     g_fill[NMAX];       // bucket fill counters
__device__ int     g_eidx[EMAX];       // CSR column indices (src node per edge)

// -------- init + degrees --------
__global__ void zero_kernel(int n) {
    int i = blockIdx.x * blockDim.x + threadIdx.x;
    if (i < n) { g_onorm[i] = 0.f; g_inorm[i] = 0.f; g_fill[i] = 0; }
}

__global__ void deg_kernel(const int* __restrict__ src, const int* __restrict__ dst, int e) {
    int i = blockIdx.x * blockDim.x + threadIdx.x;
    if (i < e) {
        atomicAdd(&g_onorm[src[i]], 1.0f);
        atomicAdd(&g_inorm[dst[i]], 1.0f);
    }
}

// -------- exclusive scan of in-degrees -> g_rowptr (3 kernels) --------
__global__ void scan1_kernel(int n) {
    __shared__ int sd[1024];
    int t = threadIdx.x, b = blockIdx.x;
    int i = b * 1024 + t;
    int d = (i < n) ? (int)g_inorm[i] : 0;   // g_inorm still holds float counts here
    sd[t] = d;
    __syncthreads();
#pragma unroll
    for (int off = 1; off < 1024; off <<= 1) {
        int v = (t >= off) ? sd[t - off] : 0;
        __syncthreads();
        sd[t] += v;
        __syncthreads();
    }
    if (i < n) g_rowptr[i] = sd[t] - d;      // exclusive within block
    if (t == 1023) g_bsum[b] = sd[1023];
}

__global__ void scan2_kernel(int nb) {
    __shared__ int sd[NB_SCAN];
    int t = threadIdx.x;
    int d = (t < nb) ? g_bsum[t] : 0;
    sd[t] = d;
    __syncthreads();
#pragma unroll
    for (int off = 1; off < NB_SCAN; off <<= 1) {
        int v = (t >= off) ? sd[t - off] : 0;
        __syncthreads();
        sd[t] += v;
        __syncthreads();
    }
    if (t < nb) g_bsum[t] = sd[t] - d;       // exclusive block offsets
}

__global__ void scan3_kernel(int n, int e) {
    int i = blockIdx.x * blockDim.x + threadIdx.x;
    if (i < n) g_rowptr[i] += g_bsum[i >> 10];
    if (i == 0) g_rowptr[n] = e;
}

// -------- CSR bucket fill --------
__global__ void fill_kernel(const int* __restrict__ src, const int* __restrict__ dst, int e) {
    int i = blockIdx.x * blockDim.x + threadIdx.x;
    if (i < e) {
        int d = dst[i];
        int pos = atomicAdd(&g_fill[d], 1);
        g_eidx[g_rowptr[d] + pos] = src[i];
    }
}

// -------- norms --------
__global__ void norm_kernel(int n) {
    int i = blockIdx.x * blockDim.x + threadIdx.x;
    if (i < n) {
        g_onorm[i] = rsqrtf(fmaxf(g_onorm[i], 1.0f));
        g_inorm[i] = rsqrtf(fmaxf(g_inorm[i], 1.0f));
    }
}

// -------- layer-0 message prep: hs = fp16(feats * out_norm) --------
__global__ void conv0_kernel(const float4* __restrict__ feats4, int n8) {
    int i = blockIdx.x * blockDim.x + threadIdx.x;
    if (i >= n8) return;
    int node = i >> 3, q = i & 7;
    float s = g_onorm[node];
    float4 v0 = feats4[node * 16 + q * 2];
    float4 v1 = feats4[node * 16 + q * 2 + 1];
    __half2 a0 = __floats2half2_rn(v0.x * s, v0.y * s);
    __half2 a1 = __floats2half2_rn(v0.z * s, v0.w * s);
    __half2 a2 = __floats2half2_rn(v1.x * s, v1.y * s);
    __half2 a3 = __floats2half2_rn(v1.z * s, v1.w * s);
    uint4 u = make_uint4(*(uint32_t*)&a0, *(uint32_t*)&a1, *(uint32_t*)&a2, *(uint32_t*)&a3);
    *(uint4*)(g_hs + (size_t)node * 64 + q * 8) = u;
}

// -------- CSR aggregation: agg[node] = sum over in-edges of hs[src] (fp32 acc) --------
__device__ __forceinline__ void acc_halfs(float acc[8], uint4 u) {
    __half2 h0 = *(__half2*)&u.x, h1 = *(__half2*)&u.y;
    __half2 h2 = *(__half2*)&u.z, h3 = *(__half2*)&u.w;
    float2 f0 = __half22float2(h0), f1 = __half22float2(h1);
    float2 f2 = __half22float2(h2), f3 = __half22float2(h3);
    acc[0] += f0.x; acc[1] += f0.y; acc[2] += f1.x; acc[3] += f1.y;
    acc[4] += f2.x; acc[5] += f2.y; acc[6] += f3.x; acc[7] += f3.y;
}

__global__ __launch_bounds__(256)
void agg_kernel(int n8) {
    int gi = blockIdx.x * blockDim.x + threadIdx.x;
    if (gi >= n8) return;
    int node = gi >> 3, q = gi & 7;
    int beg = g_rowptr[node], end = g_rowptr[node + 1];
    float acc[8];
#pragma unroll
    for (int c = 0; c < 8; c++) acc[c] = 0.f;

    const __half* hs = g_hs;
    int i = beg;
    for (; i + 2 <= end; i += 2) {
        int s0 = __ldg(g_eidx + i);
        int s1 = __ldg(g_eidx + i + 1);
        uint4 u0 = *(const uint4*)(hs + (size_t)s0 * 64 + q * 8);
        uint4 u1 = *(const uint4*)(hs + (size_t)s1 * 64 + q * 8);
        acc_halfs(acc, u0);
        acc_halfs(acc, u1);
    }
    if (i < end) {
        int s0 = __ldg(g_eidx + i);
        uint4 u0 = *(const uint4*)(hs + (size_t)s0 * 64 + q * 8);
        acc_halfs(acc, u0);
    }
    float* aggf = (float*)g_agg;
    *(float4*)(aggf + (size_t)node * 64 + q * 8)     = make_float4(acc[0], acc[1], acc[2], acc[3]);
    *(float4*)(aggf + (size_t)node * 64 + q * 8 + 4) = make_float4(acc[4], acc[5], acc[6], acc[7]);
}

// -------- fused layer GEMM: t = [agg*in_norm | h] @ [convW; resW] + b ; LN ; relu ;
//          h <- t ; h_final (+)= t ; hs <- fp16(t*out_norm) --------
__global__ __launch_bounds__(256, 2)
void fused_kernel(const float* __restrict__ h_ext, int use_ext,
                  const float* __restrict__ convW, const float* __restrict__ resW,
                  const float* __restrict__ conv_b, const float* __restrict__ res_b,
                  const float* __restrict__ ln_g,  const float* __restrict__ ln_b,
                  int n, int first, int write_hs)
{
    extern __shared__ float sm[];
    float* As = sm;               // [128][SA], k-major (transposed)
    float* Ws = sm + 128 * SA;    // [128][64]
    const float* aggr = (const float*)g_agg;
    const float* h_in = use_ext ? h_ext : (const float*)g_h;

    int t = threadIdx.x;
    int base = blockIdx.x * 128;

    for (int i = t; i < 2048; i += 256) {
        int k = i >> 4, c4 = i & 15;
        const float* wsrc = (k < 64) ? (convW + k * 64) : (resW + (k - 64) * 64);
        *(float4*)(Ws + k * 64 + c4 * 4) = *(const float4*)(wsrc + c4 * 4);
    }
    for (int i = t; i < 2048; i += 256) {
        int r = i >> 4, k4 = i & 15;
        int node = base + r;
        float4 v = make_float4(0.f, 0.f, 0.f, 0.f);
        float nn = 0.f;
        if (node < n) {
            v = *(const float4*)(aggr + node * 64 + k4 * 4);
            nn = g_inorm[node];
        }
        int k = k4 * 4;
        As[(k + 0) * SA + r] = v.x * nn;
        As[(k + 1) * SA + r] = v.y * nn;
        As[(k + 2) * SA + r] = v.z * nn;
        As[(k + 3) * SA + r] = v.w * nn;
    }
    for (int i = t; i < 2048; i += 256) {
        int r = i >> 4, k4 = i & 15;
        int node = base + r;
        float4 v = make_float4(0.f, 0.f, 0.f, 0.f);
        if (node < n) v = *(const float4*)(h_in + node * 64 + k4 * 4);
        int k = 64 + k4 * 4;
        As[(k + 0) * SA + r] = v.x;
        As[(k + 1) * SA + r] = v.y;
        As[(k + 2) * SA + r] = v.z;
        As[(k + 3) * SA + r] = v.w;
    }
    __syncthreads();

    int rg = t >> 3;      // rows rg*4 .. rg*4+3
    int cg = t & 7;       // cols cg*8 .. cg*8+7
    float acc[4][8];
#pragma unroll
    for (int r = 0; r < 4; r++)
#pragma unroll
        for (int c = 0; c < 8; c++) acc[r][c] = 0.f;

#pragma unroll 8
    for (int k = 0; k < 128; k++) {
        float4 a  = *(const float4*)(As + k * SA + rg * 4);
        float4 w0 = *(const float4*)(Ws + k * 64 + cg * 8);
        float4 w1 = *(const float4*)(Ws + k * 64 + cg * 8 + 4);
        float av[4] = {a.x, a.y, a.z, a.w};
        float wv[8] = {w0.x, w0.y, w0.z, w0.w, w1.x, w1.y, w1.z, w1.w};
#pragma unroll
        for (int r = 0; r < 4; r++)
#pragma unroll
            for (int c = 0; c < 8; c++)
                acc[r][c] += av[r] * wv[c];
    }

    int col0 = cg * 8;
    float bb[8], gg[8], lb[8];
#pragma unroll
    for (int c = 0; c < 8; c++) {
        bb[c] = conv_b[col0 + c] + res_b[col0 + c];
        gg[c] = ln_g[col0 + c];
        lb[c] = ln_b[col0 + c];
    }
    float* hout = (float*)g_h;
    float* hf   = (float*)g_hf;

#pragma unroll
    for (int r = 0; r < 4; r++) {
        float v[8]; float s = 0.f, sq = 0.f;
#pragma unroll
        for (int c = 0; c < 8; c++) {
            v[c] = acc[r][c] + bb[c];
            s += v[c]; sq += v[c] * v[c];
        }
#pragma unroll
        for (int m = 1; m < 8; m <<= 1) {
            s  += __shfl_xor_sync(0xffffffffu, s,  m);
            sq += __shfl_xor_sync(0xffffffffu, sq, m);
        }
        float mu  = s * (1.f / 64.f);
        float var = sq * (1.f / 64.f) - mu * mu;
        float inv = rsqrtf(var + 1e-5f);
        int node = base + rg * 4 + r;
        if (node < n) {
            float o[8];
#pragma unroll
            for (int c = 0; c < 8; c++) {
                float x = (v[c] - mu) * inv * gg[c] + lb[c];
                o[c] = fmaxf(x, 0.f);
            }
            float4 o0 = make_float4(o[0], o[1], o[2], o[3]);
            float4 o1 = make_float4(o[4], o[5], o[6], o[7]);
            *(float4*)(hout + node * 64 + col0)     = o0;
            *(float4*)(hout + node * 64 + col0 + 4) = o1;
            float4* fp = (float4*)(hf + node * 64 + col0);
            if (first) {
                fp[0] = o0; fp[1] = o1;
            } else {
                float4 a0 = fp[0], a1 = fp[1];
                a0.x += o0.x; a0.y += o0.y; a0.z += o0.z; a0.w += o0.w;
                a1.x += o1.x; a1.y += o1.y; a1.z += o1.z; a1.w += o1.w;
                fp[0] = a0; fp[1] = a1;
            }
            if (write_hs) {
                float on = g_onorm[node];
                __half2 a0h = __floats2half2_rn(o[0] * on, o[1] * on);
                __half2 a1h = __floats2half2_rn(o[2] * on, o[3] * on);
                __half2 a2h = __floats2half2_rn(o[4] * on, o[5] * on);
                __half2 a3h = __floats2half2_rn(o[6] * on, o[7] * on);
                uint4 u = make_uint4(*(uint32_t*)&a0h, *(uint32_t*)&a1h,
                                     *(uint32_t*)&a2h, *(uint32_t*)&a3h);
                *(uint4*)(g_hs + (size_t)node * 64 + col0) = u;
            }
        }
    }
}

// -------- final prediction GEMM: out = h_final @ predW + pred_b (K = 64) --------
__global__ __launch_bounds__(256, 2)
void pred_kernel(const float* __restrict__ predW, const float* __restrict__ pred_b,
                 float* __restrict__ out, int n)
{
    extern __shared__ float sm[];
    float* As = sm;              // [64][SA]
    float* Ws = sm + 64 * SA;    // [64][64]
    const float* hfin = (const float*)g_hf;

    int t = threadIdx.x;
    int base = blockIdx.x * 128;

    for (int i = t; i < 1024; i += 256) {
        int k = i >> 4, c4 = i & 15;
        *(float4*)(Ws + k * 64 + c4 * 4) = *(const float4*)(predW + k * 64 + c4 * 4);
    }
    for (int i = t; i < 2048; i += 256) {
        int r = i >> 4, k4 = i & 15;
        int node = base + r;
        float4 v = make_float4(0.f, 0.f, 0.f, 0.f);
        if (node < n) v = *(const float4*)(hfin + node * 64 + k4 * 4);
        int k = k4 * 4;
        As[(k + 0) * SA + r] = v.x;
        As[(k + 1) * SA + r] = v.y;
        As[(k + 2) * SA + r] = v.z;
        As[(k + 3) * SA + r] = v.w;
    }
    __syncthreads();

    int rg = t >> 3, cg = t & 7;
    float acc[4][8];
#pragma unroll
    for (int r = 0; r < 4; r++)
#pragma unroll
        for (int c = 0; c < 8; c++) acc[r][c] = 0.f;

#pragma unroll 8
    for (int k = 0; k < 64; k++) {
        float4 a  = *(const float4*)(As + k * SA + rg * 4);
        float4 w0 = *(const float4*)(Ws + k * 64 + cg * 8);
        float4 w1 = *(const float4*)(Ws + k * 64 + cg * 8 + 4);
        float av[4] = {a.x, a.y, a.z, a.w};
        float wv[8] = {w0.x, w0.y, w0.z, w0.w, w1.x, w1.y, w1.z, w1.w};
#pragma unroll
        for (int r = 0; r < 4; r++)
#pragma unroll
            for (int c = 0; c < 8; c++)
                acc[r][c] += av[r] * wv[c];
    }

    int col0 = cg * 8;
    float bb[8];
#pragma unroll
    for (int c = 0; c < 8; c++) bb[c] = pred_b[col0 + c];

#pragma unroll
    for (int r = 0; r < 4; r++) {
        int node = base + rg * 4 + r;
        if (node < n) {
            float4 o0 = make_float4(acc[r][0] + bb[0], acc[r][1] + bb[1],
                                    acc[r][2] + bb[2], acc[r][3] + bb[3]);
            float4 o1 = make_float4(acc[r][4] + bb[4], acc[r][5] + bb[5],
                                    acc[r][6] + bb[6], acc[r][7] + bb[7]);
            *(float4*)(out + node * 64 + col0)     = o0;
            *(float4*)(out + node * 64 + col0 + 4) = o1;
        }
    }
}

// -------- host entry --------
extern "C" void kernel_launch(void* const* d_in, const int* in_sizes, int n_in,
                              void* d_out, int out_size)
{
    const float* feats  = (const float*)d_in[0];
    const int*   src    = (const int*)  d_in[1];
    const int*   dst    = (const int*)  d_in[2];
    const float* convW  = (const float*)d_in[3];
    const float* conv_b = (const float*)d_in[4];
    const float* resW   = (const float*)d_in[5];
    const float* res_b  = (const float*)d_in[6];
    const float* ln_g   = (const float*)d_in[7];
    const float* ln_b   = (const float*)d_in[8];
    const float* predW  = (const float*)d_in[9];
    const float* pred_b = (const float*)d_in[10];

    int n = in_sizes[0] / 64;
    int e = in_sizes[1];
    int nb = (n + 1023) / 1024;

    const int smem_fused = (128 * SA + 128 * 64) * 4;  // 100352 B
    const int smem_pred  = (64 * SA + 64 * 64) * 4;    //  50176 B
    cudaFuncSetAttribute(fused_kernel, cudaFuncAttributeMaxDynamicSharedMemorySize, smem_fused);
    cudaFuncSetAttribute(pred_kernel,  cudaFuncAttributeMaxDynamicSharedMemorySize, smem_pred);

    // ---- degrees + CSR build (once) ----
    zero_kernel<<<(n + 255) / 256, 256>>>(n);
    deg_kernel<<<(e + 255) / 256, 256>>>(src, dst, e);
    scan1_kernel<<<nb, 1024>>>(n);                 // reads float counts in g_inorm
    scan2_kernel<<<1, NB_SCAN>>>(nb);
    scan3_kernel<<<(n + 255) / 256, 256>>>(n, e);
    fill_kernel<<<(e + 255) / 256, 256>>>(src, dst, e);
    norm_kernel<<<(n + 255) / 256, 256>>>(n);      // counts -> rsqrt norms

    int n8 = n * 8;
    int gb = (n + 127) / 128;

    conv0_kernel<<<(n8 + 255) / 256, 256>>>((const float4*)feats, n8);

    for (int l = 0; l < 3; l++) {
        int use_ext = (l == 0) ? 1 : 0;
        agg_kernel<<<(n8 + 255) / 256, 256>>>(n8);
        fused_kernel<<<gb, 256, smem_fused>>>(feats, use_ext,
                                              convW + l * 4096, resW + l * 4096,
                                              conv_b + l * 64, res_b + l * 64,
                                              ln_g + l * 64, ln_b + l * 64,
                                              n, (l == 0) ? 1 : 0, (l < 2) ? 1 : 0);
    }
    pred_kernel<<<gb, 256, smem_pred>>>(predW, pred_b, (float*)d_out, n);
}

// round 4
// speedup vs baseline: 1.5794x; 1.0339x over previous
#include <cuda_runtime.h>
#include <cuda_fp16.h>
#include <cstdint>

#define NMAX 100000
#define EMAX 1000000
#define SA 132        // smem A row stride (floats)
#define NB_SCAN 128   // >= ceil(NMAX/1024)

// -------- persistent device scratch --------
__device__ __half  g_hs [NMAX * 64];   // scaled messages h*out_norm, fp16
__device__ float4  g_agg[NMAX * 16];   // aggregation result (fp32)
__device__ float4  g_h  [NMAX * 16];   // current layer activations
__device__ float4  g_hf [NMAX * 16];   // jumping-knowledge accumulator
__device__ float   g_onorm[NMAX];      // out-degree -> rsqrt norm
__device__ float   g_inorm[NMAX];      // in-degree  -> rsqrt norm
__device__ int     g_rowptr[NMAX + 1]; // dst-CSR row pointers
__device__ int     g_bsum[NB_SCAN];    // scan block sums
__device__ int     g_fill[NMAX];       // bucket fill counters
__device__ int     g_eidx[EMAX];       // CSR column indices (src node per edge)

// -------- packed f32x2 helpers (Blackwell FFMA2) --------
__device__ __forceinline__ unsigned long long pk2(float lo, float hi) {
    unsigned long long r;
    asm("mov.b64 %0, {%1, %2};" : "=l"(r) : "f"(lo), "f"(hi));
    return r;
}
__device__ __forceinline__ void upk2(float& lo, float& hi, unsigned long long v) {
    asm("mov.b64 {%0, %1}, %2;" : "=f"(lo), "=f"(hi) : "l"(v));
}
#define FMA2(acc, a, b) asm("fma.rn.f32x2 %0, %1, %2, %0;" : "+l"(acc) : "l"(a), "l"(b))

// -------- init + degrees --------
__global__ void zero_kernel(int n) {
    int i = blockIdx.x * blockDim.x + threadIdx.x;
    if (i < n) { g_onorm[i] = 0.f; g_inorm[i] = 0.f; g_fill[i] = 0; }
}

__global__ void deg_kernel(const int* __restrict__ src, const int* __restrict__ dst, int e) {
    int i = blockIdx.x * blockDim.x + threadIdx.x;
    if (i < e) {
        atomicAdd(&g_onorm[src[i]], 1.0f);
        atomicAdd(&g_inorm[dst[i]], 1.0f);
    }
}

// -------- exclusive scan of in-degrees -> g_rowptr --------
__global__ void scan1_kernel(int n) {
    __shared__ int sd[1024];
    int t = threadIdx.x, b = blockIdx.x;
    int i = b * 1024 + t;
    int d = (i < n) ? (int)g_inorm[i] : 0;   // g_inorm still holds float counts here
    sd[t] = d;
    __syncthreads();
#pragma unroll
    for (int off = 1; off < 1024; off <<= 1) {
        int v = (t >= off) ? sd[t - off] : 0;
        __syncthreads();
        sd[t] += v;
        __syncthreads();
    }
    if (i < n) g_rowptr[i] = sd[t] - d;
    if (t == 1023) g_bsum[b] = sd[1023];
}

__global__ void scan2_kernel(int nb) {
    __shared__ int sd[NB_SCAN];
    int t = threadIdx.x;
    int d = (t < nb) ? g_bsum[t] : 0;
    sd[t] = d;
    __syncthreads();
#pragma unroll
    for (int off = 1; off < NB_SCAN; off <<= 1) {
        int v = (t >= off) ? sd[t - off] : 0;
        __syncthreads();
        sd[t] += v;
        __syncthreads();
    }
    if (t < nb) g_bsum[t] = sd[t] - d;
}

__global__ void scan3_kernel(int n, int e) {
    int i = blockIdx.x * blockDim.x + threadIdx.x;
    if (i < n) g_rowptr[i] += g_bsum[i >> 10];
    if (i == 0) g_rowptr[n] = e;
}

__global__ void fill_kernel(const int* __restrict__ src, const int* __restrict__ dst, int e) {
    int i = blockIdx.x * blockDim.x + threadIdx.x;
    if (i < e) {
        int d = dst[i];
        int pos = atomicAdd(&g_fill[d], 1);
        g_eidx[g_rowptr[d] + pos] = src[i];
    }
}

__global__ void norm_kernel(int n) {
    int i = blockIdx.x * blockDim.x + threadIdx.x;
    if (i < n) {
        g_onorm[i] = rsqrtf(fmaxf(g_onorm[i], 1.0f));
        g_inorm[i] = rsqrtf(fmaxf(g_inorm[i], 1.0f));
    }
}

// -------- layer-0 message prep: hs = fp16(feats * out_norm) --------
__global__ void conv0_kernel(const float4* __restrict__ feats4, int n8) {
    int i = blockIdx.x * blockDim.x + threadIdx.x;
    if (i >= n8) return;
    int node = i >> 3, q = i & 7;
    float s = g_onorm[node];
    float4 v0 = feats4[node * 16 + q * 2];
    float4 v1 = feats4[node * 16 + q * 2 + 1];
    __half2 a0 = __floats2half2_rn(v0.x * s, v0.y * s);
    __half2 a1 = __floats2half2_rn(v0.z * s, v0.w * s);
    __half2 a2 = __floats2half2_rn(v1.x * s, v1.y * s);
    __half2 a3 = __floats2half2_rn(v1.z * s, v1.w * s);
    uint4 u = make_uint4(*(uint32_t*)&a0, *(uint32_t*)&a1, *(uint32_t*)&a2, *(uint32_t*)&a3);
    *(uint4*)(g_hs + (size_t)node * 64 + q * 8) = u;
}

// -------- CSR aggregation: agg[node] = sum of hs[src] over in-edges (fp32 acc) --------
__device__ __forceinline__ void acc_halfs(float acc[8], uint4 u) {
    __half2 h0 = *(__half2*)&u.x, h1 = *(__half2*)&u.y;
    __half2 h2 = *(__half2*)&u.z, h3 = *(__half2*)&u.w;
    float2 f0 = __half22float2(h0), f1 = __half22float2(h1);
    float2 f2 = __half22float2(h2), f3 = __half22float2(h3);
    acc[0] += f0.x; acc[1] += f0.y; acc[2] += f1.x; acc[3] += f1.y;
    acc[4] += f2.x; acc[5] += f2.y; acc[6] += f3.x; acc[7] += f3.y;
}

__global__ __launch_bounds__(256)
void agg_kernel(int n8) {
    int gi = blockIdx.x * blockDim.x + threadIdx.x;
    if (gi >= n8) return;
    int node = gi >> 3, q = gi & 7;
    int beg = g_rowptr[node], end = g_rowptr[node + 1];
    float acc[8];
#pragma unroll
    for (int c = 0; c < 8; c++) acc[c] = 0.f;

    const __half* hs = g_hs;
    int i = beg;
    // unroll-4: four independent gathers in flight (MLP)
    for (; i + 4 <= end; i += 4) {
        int s0 = __ldg(g_eidx + i);
        int s1 = __ldg(g_eidx + i + 1);
        int s2 = __ldg(g_eidx + i + 2);
        int s3 = __ldg(g_eidx + i + 3);
        uint4 u0 = *(const uint4*)(hs + (size_t)s0 * 64 + q * 8);
        uint4 u1 = *(const uint4*)(hs + (size_t)s1 * 64 + q * 8);
        uint4 u2 = *(const uint4*)(hs + (size_t)s2 * 64 + q * 8);
        uint4 u3 = *(const uint4*)(hs + (size_t)s3 * 64 + q * 8);
        acc_halfs(acc, u0);
        acc_halfs(acc, u1);
        acc_halfs(acc, u2);
        acc_halfs(acc, u3);
    }
    if (i + 2 <= end) {
        int s0 = __ldg(g_eidx + i);
        int s1 = __ldg(g_eidx + i + 1);
        uint4 u0 = *(const uint4*)(hs + (size_t)s0 * 64 + q * 8);
        uint4 u1 = *(const uint4*)(hs + (size_t)s1 * 64 + q * 8);
        acc_halfs(acc, u0);
        acc_halfs(acc, u1);
        i += 2;
    }
    if (i < end) {
        int s0 = __ldg(g_eidx + i);
        uint4 u0 = *(const uint4*)(hs + (size_t)s0 * 64 + q * 8);
        acc_halfs(acc, u0);
    }
    float* aggf = (float*)g_agg;
    *(float4*)(aggf + (size_t)node * 64 + q * 8)     = make_float4(acc[0], acc[1], acc[2], acc[3]);
    *(float4*)(aggf + (size_t)node * 64 + q * 8 + 4) = make_float4(acc[4], acc[5], acc[6], acc[7]);
}

// -------- fused layer GEMM (f32x2 packed FMA): t = [agg*in_norm | h] @ [convW; resW]
//          + b ; LN ; relu ; h <- t ; h_final (+)= t ; hs <- fp16(t*out_norm) --------
__global__ __launch_bounds__(256, 2)
void fused_kernel(const float* __restrict__ h_ext, int use_ext,
                  const float* __restrict__ convW, const float* __restrict__ resW,
                  const float* __restrict__ conv_b, const float* __restrict__ res_b,
                  const float* __restrict__ ln_g,  const float* __restrict__ ln_b,
                  int n, int first, int write_hs)
{
    extern __shared__ float sm[];
    float* As = sm;               // [128][SA], k-major (transposed)
    float* Ws = sm + 128 * SA;    // [128][64]
    const float* aggr = (const float*)g_agg;
    const float* h_in = use_ext ? h_ext : (const float*)g_h;

    int t = threadIdx.x;
    int base = blockIdx.x * 128;

    for (int i = t; i < 2048; i += 256) {
        int k = i >> 4, c4 = i & 15;
        const float* wsrc = (k < 64) ? (convW + k * 64) : (resW + (k - 64) * 64);
        *(float4*)(Ws + k * 64 + c4 * 4) = *(const float4*)(wsrc + c4 * 4);
    }
    for (int i = t; i < 2048; i += 256) {
        int r = i >> 4, k4 = i & 15;
        int node = base + r;
        float4 v = make_float4(0.f, 0.f, 0.f, 0.f);
        float nn = 0.f;
        if (node < n) {
            v = *(const float4*)(aggr + node * 64 + k4 * 4);
            nn = g_inorm[node];
        }
        int k = k4 * 4;
        As[(k + 0) * SA + r] = v.x * nn;
        As[(k + 1) * SA + r] = v.y * nn;
        As[(k + 2) * SA + r] = v.z * nn;
        As[(k + 3) * SA + r] = v.w * nn;
    }
    for (int i = t; i < 2048; i += 256) {
        int r = i >> 4, k4 = i & 15;
        int node = base + r;
        float4 v = make_float4(0.f, 0.f, 0.f, 0.f);
        if (node < n) v = *(const float4*)(h_in + node * 64 + k4 * 4);
        int k = 64 + k4 * 4;
        As[(k + 0) * SA + r] = v.x;
        As[(k + 1) * SA + r] = v.y;
        As[(k + 2) * SA + r] = v.z;
        As[(k + 3) * SA + r] = v.w;
    }
    __syncthreads();

    int rg = t >> 3;      // rows rg*4 .. rg*4+3
    int cg = t & 7;       // cols cg*8 .. cg*8+7
    unsigned long long acc2[4][4];   // [row][colpair], packed f32x2
#pragma unroll
    for (int r = 0; r < 4; r++)
#pragma unroll
        for (int c = 0; c < 4; c++) acc2[r][c] = 0ull;

#pragma unroll 8
    for (int k = 0; k < 128; k++) {
        float4 a = *(const float4*)(As + k * SA + rg * 4);
        ulonglong4 w = *(const ulonglong4*)(Ws + k * 64 + cg * 8);  // 4 packed col-pairs
        unsigned long long ap[4];
        ap[0] = pk2(a.x, a.x); ap[1] = pk2(a.y, a.y);
        ap[2] = pk2(a.z, a.z); ap[3] = pk2(a.w, a.w);
#pragma unroll
        for (int r = 0; r < 4; r++) {
            FMA2(acc2[r][0], ap[r], w.x);
            FMA2(acc2[r][1], ap[r], w.y);
            FMA2(acc2[r][2], ap[r], w.z);
            FMA2(acc2[r][3], ap[r], w.w);
        }
    }

    // epilogue
    int col0 = cg * 8;
    float bb[8], gg[8], lb[8];
#pragma unroll
    for (int c = 0; c < 8; c++) {
        bb[c] = conv_b[col0 + c] + res_b[col0 + c];
        gg[c] = ln_g[col0 + c];
        lb[c] = ln_b[col0 + c];
    }
    float* hout = (float*)g_h;
    float* hf   = (float*)g_hf;

#pragma unroll
    for (int r = 0; r < 4; r++) {
        float v[8]; float s = 0.f, sq = 0.f;
#pragma unroll
        for (int c = 0; c < 4; c++) {
            float lo, hi;
            upk2(lo, hi, acc2[r][c]);
            v[2 * c] = lo + bb[2 * c];
            v[2 * c + 1] = hi + bb[2 * c + 1];
        }
#pragma unroll
        for (int c = 0; c < 8; c++) { s += v[c]; sq += v[c] * v[c]; }
#pragma unroll
        for (int m = 1; m < 8; m <<= 1) {
            s  += __shfl_xor_sync(0xffffffffu, s,  m);
            sq += __shfl_xor_sync(0xffffffffu, sq, m);
        }
        float mu  = s * (1.f / 64.f);
        float var = sq * (1.f / 64.f) - mu * mu;
        float inv = rsqrtf(var + 1e-5f);
        int node = base + rg * 4 + r;
        if (node < n) {
            float o[8];
#pragma unroll
            for (int c = 0; c < 8; c++) {
                float x = (v[c] - mu) * inv * gg[c] + lb[c];
                o[c] = fmaxf(x, 0.f);
            }
            float4 o0 = make_float4(o[0], o[1], o[2], o[3]);
            float4 o1 = make_float4(o[4], o[5], o[6], o[7]);
            *(float4*)(hout + node * 64 + col0)     = o0;
            *(float4*)(hout + node * 64 + col0 + 4) = o1;
            float4* fp = (float4*)(hf + node * 64 + col0);
            if (first) {
                fp[0] = o0; fp[1] = o1;
            } else {
                float4 a0 = fp[0], a1 = fp[1];
                a0.x += o0.x; a0.y += o0.y; a0.z += o0.z; a0.w += o0.w;
                a1.x += o1.x; a1.y += o1.y; a1.z += o1.z; a1.w += o1.w;
                fp[0] = a0; fp[1] = a1;
            }
            if (write_hs) {
                float on = g_onorm[node];
                __half2 a0h = __floats2half2_rn(o[0] * on, o[1] * on);
                __half2 a1h = __floats2half2_rn(o[2] * on, o[3] * on);
                __half2 a2h = __floats2half2_rn(o[4] * on, o[5] * on);
                __half2 a3h = __floats2half2_rn(o[6] * on, o[7] * on);
                uint4 u = make_uint4(*(uint32_t*)&a0h, *(uint32_t*)&a1h,
                                     *(uint32_t*)&a2h, *(uint32_t*)&a3h);
                *(uint4*)(g_hs + (size_t)node * 64 + col0) = u;
            }
        }
    }
}

// -------- final prediction GEMM (f32x2): out = h_final @ predW + pred_b --------
__global__ __launch_bounds__(256, 2)
void pred_kernel(const float* __restrict__ predW, const float* __restrict__ pred_b,
                 float* __restrict__ out, int n)
{
    extern __shared__ float sm[];
    float* As = sm;              // [64][SA]
    float* Ws = sm + 64 * SA;    // [64][64]
    const float* hfin = (const float*)g_hf;

    int t = threadIdx.x;
    int base = blockIdx.x * 128;

    for (int i = t; i < 1024; i += 256) {
        int k = i >> 4, c4 = i & 15;
        *(float4*)(Ws + k * 64 + c4 * 4) = *(const float4*)(predW + k * 64 + c4 * 4);
    }
    for (int i = t; i < 2048; i += 256) {
        int r = i >> 4, k4 = i & 15;
        int node = base + r;
        float4 v = make_float4(0.f, 0.f, 0.f, 0.f);
        if (node < n) v = *(const float4*)(hfin + node * 64 + k4 * 4);
        int k = k4 * 4;
        As[(k + 0) * SA + r] = v.x;
        As[(k + 1) * SA + r] = v.y;
        As[(k + 2) * SA + r] = v.z;
        As[(k + 3) * SA + r] = v.w;
    }
    __syncthreads();

    int rg = t >> 3, cg = t & 7;
    unsigned long long acc2[4][4];
#pragma unroll
    for (int r = 0; r < 4; r++)
#pragma unroll
        for (int c = 0; c < 4; c++) acc2[r][c] = 0ull;

#pragma unroll 8
    for (int k = 0; k < 64; k++) {
        float4 a = *(const float4*)(As + k * SA + rg * 4);
        ulonglong4 w = *(const ulonglong4*)(Ws + k * 64 + cg * 8);
        unsigned long long ap[4];
        ap[0] = pk2(a.x, a.x); ap[1] = pk2(a.y, a.y);
        ap[2] = pk2(a.z, a.z); ap[3] = pk2(a.w, a.w);
#pragma unroll
        for (int r = 0; r < 4; r++) {
            FMA2(acc2[r][0], ap[r], w.x);
            FMA2(acc2[r][1], ap[r], w.y);
            FMA2(acc2[r][2], ap[r], w.z);
            FMA2(acc2[r][3], ap[r], w.w);
        }
    }

    int col0 = cg * 8;
    float bb[8];
#pragma unroll
    for (int c = 0; c < 8; c++) bb[c] = pred_b[col0 + c];

#pragma unroll
    for (int r = 0; r < 4; r++) {
        int node = base + rg * 4 + r;
        if (node < n) {
            float o[8];
#pragma unroll
            for (int c = 0; c < 4; c++) {
                float lo, hi;
                upk2(lo, hi, acc2[r][c]);
                o[2 * c] = lo + bb[2 * c];
                o[2 * c + 1] = hi + bb[2 * c + 1];
            }
            *(float4*)(out + node * 64 + col0)     = make_float4(o[0], o[1], o[2], o[3]);
            *(float4*)(out + node * 64 + col0 + 4) = make_float4(o[4], o[5], o[6], o[7]);
        }
    }
}

// -------- host entry --------
extern "C" void kernel_launch(void* const* d_in, const int* in_sizes, int n_in,
                              void* d_out, int out_size)
{
    const float* feats  = (const float*)d_in[0];
    const int*   src    = (const int*)  d_in[1];
    const int*   dst    = (const int*)  d_in[2];
    const float* convW  = (const float*)d_in[3];
    const float* conv_b = (const float*)d_in[4];
    const float* resW   = (const float*)d_in[5];
    const float* res_b  = (const float*)d_in[6];
    const float* ln_g   = (const float*)d_in[7];
    const float* ln_b   = (const float*)d_in[8];
    const float* predW  = (const float*)d_in[9];
    const float* pred_b = (const float*)d_in[10];

    int n = in_sizes[0] / 64;
    int e = in_sizes[1];
    int nb = (n + 1023) / 1024;

    const int smem_fused = (128 * SA + 128 * 64) * 4;  // 100352 B
    const int smem_pred  = (64 * SA + 64 * 64) * 4;    //  50176 B
    cudaFuncSetAttribute(fused_kernel, cudaFuncAttributeMaxDynamicSharedMemorySize, smem_fused);
    cudaFuncSetAttribute(pred_kernel,  cudaFuncAttributeMaxDynamicSharedMemorySize, smem_pred);

    // ---- degrees + CSR build (once per launch) ----
    zero_kernel<<<(n + 255) / 256, 256>>>(n);
    deg_kernel<<<(e + 255) / 256, 256>>>(src, dst, e);
    scan1_kernel<<<nb, 1024>>>(n);
    scan2_kernel<<<1, NB_SCAN>>>(nb);
    scan3_kernel<<<(n + 255) / 256, 256>>>(n, e);
    fill_kernel<<<(e + 255) / 256, 256>>>(src, dst, e);
    norm_kernel<<<(n + 255) / 256, 256>>>(n);

    int n8 = n * 8;
    int gb = (n + 127) / 128;

    conv0_kernel<<<(n8 + 255) / 256, 256>>>((const float4*)feats, n8);

    for (int l = 0; l < 3; l++) {
        int use_ext = (l == 0) ? 1 : 0;
        agg_kernel<<<(n8 + 255) / 256, 256>>>(n8);
        fused_kernel<<<gb, 256, smem_fused>>>(feats, use_ext,
                                              convW + l * 4096, resW + l * 4096,
                                              conv_b + l * 64, res_b + l * 64,
                                              ln_g + l * 64, ln_b + l * 64,
                                              n, (l == 0) ? 1 : 0, (l < 2) ? 1 : 0);
    }
    pred_kernel<<<gb, 256, smem_pred>>>(predW, pred_b, (float*)d_out, n);
}